// round 15
// baseline (speedup 1.0000x reference)
#include <cuda_runtime.h>
#include <cuda_bf16.h>
#include <cuda_fp16.h>
#include <cstdint>

#define BATCH 4
#define S_LEN 2048
#define EMB   1024
#define NH    16
#define HD    64
#define MTOT  (BATCH * S_LEN)   // 8192

// ---------------------------------------------------------------------------
// Device-global scratch (allocation-free requirement)
// ---------------------------------------------------------------------------
static __device__ __half g_A [MTOT * EMB];               // GEMM A (single fp16)
static __device__ __half g_WQ[3 * EMB * EMB];            // W_qkv^T fp16 [N=3072,K=1024]
static __device__ __half g_WP[EMB * EMB];                // W_proj^T fp16 [N=1024,K=1024]

static __device__ __half g_Q [BATCH * NH * S_LEN * HD];  // Q single fp16 (pre-scaled)
static __device__ __half g_K [BATCH * NH * S_LEN * HD];  // K single fp16
static __device__ __half g_V [BATCH * NH * S_LEN * HD];  // V single fp16

// ---------------------------------------------------------------------------
// Portable PTX helpers (compute_100-safe)
// ---------------------------------------------------------------------------
static __device__ __forceinline__ uint32_t smem_u32(const void* p) {
    uint32_t a;
    asm("{ .reg .u64 t; cvta.to.shared.u64 t, %1; cvt.u32.u64 %0, t; }" : "=r"(a) : "l"(p));
    return a;
}
static __device__ __forceinline__ void cp_async16(uint32_t dst, const void* src) {
    asm volatile("cp.async.cg.shared.global [%0], [%1], 16;" :: "r"(dst), "l"(src) : "memory");
}
#define CP_COMMIT() asm volatile("cp.async.commit_group;" ::: "memory")
#define CP_WAIT1()  asm volatile("cp.async.wait_group 1;" ::: "memory")
#define CP_WAIT2()  asm volatile("cp.async.wait_group 2;" ::: "memory")

static __device__ __forceinline__ void ldmatrix_x4(uint32_t* r, uint32_t addr) {
    asm volatile("ldmatrix.sync.aligned.m8n8.x4.shared.b16 {%0,%1,%2,%3}, [%4];"
                 : "=r"(r[0]), "=r"(r[1]), "=r"(r[2]), "=r"(r[3]) : "r"(addr));
}
static __device__ __forceinline__ void ldmatrix_x4_trans(uint32_t* r, uint32_t addr) {
    asm volatile("ldmatrix.sync.aligned.m8n8.x4.trans.shared.b16 {%0,%1,%2,%3}, [%4];"
                 : "=r"(r[0]), "=r"(r[1]), "=r"(r[2]), "=r"(r[3]) : "r"(addr));
}
static __device__ __forceinline__ void mma_f16(float* d, const uint32_t* a, const uint32_t* b) {
    asm volatile("mma.sync.aligned.m16n8k16.row.col.f32.f16.f16.f32 "
                 "{%0,%1,%2,%3}, {%4,%5,%6,%7}, {%8,%9}, {%0,%1,%2,%3};"
                 : "+f"(d[0]), "+f"(d[1]), "+f"(d[2]), "+f"(d[3])
                 : "r"(a[0]), "r"(a[1]), "r"(a[2]), "r"(a[3]), "r"(b[0]), "r"(b[1]));
}
static __device__ __forceinline__ float ex2f(float x) {
    float y;
    asm("ex2.approx.ftz.f32 %0, %1;" : "=f"(y) : "f"(x));
    return y;
}

// ---------------------------------------------------------------------------
// Pre-processing kernels
// ---------------------------------------------------------------------------
__global__ void conv_act_kernel(const float4* __restrict__ in,
                                __half2* __restrict__ o16, int n4)
{
    int i = blockIdx.x * 256 + threadIdx.x;
    if (i >= n4) return;
    float4 v = in[i];
    o16[i * 2 + 0] = __floats2half2_rn(v.x, v.y);
    o16[i * 2 + 1] = __floats2half2_rn(v.z, v.w);
}

// W [K,N] fp32 -> W^T [N,K] fp16 (tiled transpose)
__global__ void conv_wT_kernel(const float* __restrict__ W,
                               __half* __restrict__ Th, int Kd, int Nd)
{
    __shared__ float t[32][33];
    const int n0 = blockIdx.x * 32, k0 = blockIdx.y * 32;
    const int tx = threadIdx.x, ty = threadIdx.y;
#pragma unroll
    for (int j = 0; j < 32; j += 8)
        t[ty + j][tx] = W[(size_t)(k0 + ty + j) * Nd + n0 + tx];
    __syncthreads();
#pragma unroll
    for (int j = 0; j < 32; j += 8) {
        float v = t[tx][ty + j];
        Th[(size_t)(n0 + ty + j) * Kd + k0 + tx] = __float2half_rn(v);
    }
}

// ---------------------------------------------------------------------------
// Single-fp16 mma.sync GEMM: 256x128 CTA tile, 512 threads (16 warps = 8m x 2n,
// warp tile 32x64), BK=64, pitch-72 fp16 rows (144 B), 2-stage cp.async
// pipeline, 1 CTA/SM (16 warps/SM — same warp count as R13's 2x256).
// FIXED vs R14: each 64-fp16 k-row = 8 x 16B chunks (R14 loaded only 4 ->
// half of every row uninitialized -> NaN). A: 2048 chunks = 4/thread;
// B: 1024 chunks = 2/thread.
// mode 0: fp32 C (+bias). mode 1: QKV epilogue -> Q (pre-scaled), K, V
// all single fp16 in [B,H,S,D].
// ---------------------------------------------------------------------------
#define BK      64
#define GP      144                      // bytes per 64-fp16 row (72 fp16)
#define A_TILE_B (256 * GP)              // 36864 B
#define B_TILE_B (128 * GP)              // 18432 B
#define STAGE_B (A_TILE_B + B_TILE_B)    // 55296 B
#define GEMM_SMEM (2 * STAGE_B)          // 110592 B

#define QSCALE  0.1803368801111244f      // 0.125 * log2(e)

static __device__ __forceinline__ void issue_stage(
    uint32_t sstage, const __half* __restrict__ Ag, const __half* __restrict__ Bg,
    int bm0, int bn0, int K, int kof, int tid)
{
    // A: 256 rows x 8 chunks(16B) = 2048 chunks; 4 per thread
#pragma unroll
    for (int cc = 0; cc < 4; cc++) {
        const int chunk = tid * 4 + cc;
        const int r = chunk >> 3;
        const int c = chunk & 7;
        cp_async16(sstage + (uint32_t)(r * GP + c * 16),
                   Ag + (size_t)(bm0 + r) * K + kof + c * 8);
    }
    // B: 128 rows x 8 chunks = 1024 chunks; 2 per thread
#pragma unroll
    for (int cc = 0; cc < 2; cc++) {
        const int chunk = tid * 2 + cc;
        const int r = chunk >> 3;
        const int c = chunk & 7;
        cp_async16(sstage + A_TILE_B + (uint32_t)(r * GP + c * 16),
                   Bg + (size_t)(bn0 + r) * K + kof + c * 8);
    }
}

__global__ __launch_bounds__(512, 1)
void gemm_f16_kernel(
    const __half* __restrict__ Ag, const __half* __restrict__ Bg,
    const float* __restrict__ bias, float* __restrict__ C,
    int M, int N, int K, int mode,
    __half* __restrict__ kg, __half* __restrict__ qg, __half* __restrict__ vg)
{
    extern __shared__ char smem[];
    const uint32_t sbase = smem_u32(smem);
    const int tid  = threadIdx.x;
    const int wid  = tid >> 5;
    const int lane = tid & 31;
    const int bm0 = blockIdx.y * 256;
    const int bn0 = blockIdx.x * 128;

    const int wm = (wid & 7) * 32;       // warp m offset (8 positions)
    const int wn = (wid >> 3) * 64;      // warp n offset (2 positions)

    float acc[2][8][4];
#pragma unroll
    for (int i = 0; i < 2; i++)
#pragma unroll
        for (int j = 0; j < 8; j++)
#pragma unroll
            for (int c = 0; c < 4; c++) acc[i][j][c] = 0.f;

    const int nk = K / BK;   // 16

    issue_stage(sbase + 0 * STAGE_B, Ag, Bg, bm0, bn0, K, 0, tid);
    CP_COMMIT();
    issue_stage(sbase + 1 * STAGE_B, Ag, Bg, bm0, bn0, K, BK, tid);
    CP_COMMIT();

    const uint32_t a_off = (uint32_t)(lane & 15) * GP + (uint32_t)(lane >> 4) * 16;
    const uint32_t b_off = ((uint32_t)((lane >> 4) * 8 + (lane & 7))) * GP
                         + (uint32_t)((lane >> 3) & 1) * 16;

    for (int it = 0; it < nk; it++) {
        CP_WAIT1();
        __syncthreads();
        const uint32_t st = sbase + (it & 1) * STAGE_B;
#pragma unroll
        for (int ks = 0; ks < 4; ks++) {
            uint32_t a4[2][4];
#pragma unroll
            for (int i = 0; i < 2; i++) {
                const uint32_t ro = st + (uint32_t)(wm + i * 16) * GP
                                  + (uint32_t)(ks * 32) + a_off;
                ldmatrix_x4(a4[i], ro);
            }
#pragma unroll
            for (int jp = 0; jp < 4; jp++) {
                uint32_t b4[4];
                const uint32_t ro = st + A_TILE_B + (uint32_t)(wn + jp * 16) * GP
                                  + (uint32_t)(ks * 32) + b_off;
                ldmatrix_x4(b4, ro);
                const int j0 = jp * 2, j1 = j0 + 1;
#pragma unroll
                for (int i = 0; i < 2; i++) {
                    mma_f16(acc[i][j0], a4[i], &b4[0]);
                    mma_f16(acc[i][j1], a4[i], &b4[2]);
                }
            }
        }
        __syncthreads();
        if (it + 2 < nk)
            issue_stage(st, Ag, Bg, bm0, bn0, K, (it + 2) * BK, tid);
        CP_COMMIT();
    }

    const int lr = lane >> 2;
    const int lc = (lane & 3) * 2;
#pragma unroll
    for (int i = 0; i < 2; i++) {
#pragma unroll
        for (int j = 0; j < 8; j++) {
            const int col = bn0 + wn + j * 8 + lc;
            const float bx = bias[col], by = bias[col + 1];
#pragma unroll
            for (int h2 = 0; h2 < 2; h2++) {
                const int row = bm0 + wm + i * 16 + lr + h2 * 8;
                float vx = acc[i][j][h2 * 2 + 0] + bx;
                float vy = acc[i][j][h2 * 2 + 1] + by;
                if (mode == 0) {
                    float2 v = make_float2(vx, vy);
                    *(float2*)&C[(size_t)row * N + col] = v;
                } else {
                    const int sec = col >> 10;
                    const int hh  = (col >> 6) & 15;
                    const int d   = col & 63;
                    const int b_  = row >> 11;
                    const int s   = row & 2047;
                    const size_t off = (((size_t)(b_ * NH + hh)) * S_LEN + s) * HD + d;
                    if (sec == 1) { vx *= QSCALE; vy *= QSCALE; }
                    __half* dst = (sec == 0) ? kg : ((sec == 1) ? qg : vg);
                    *(__half2*)&dst[off] = __floats2half2_rn(vx, vy);
                }
            }
        }
    }
}

// ---------------------------------------------------------------------------
// Flash attention (causal), single-fp16 operands everywhere (R13, unchanged).
// Block: 128 q-rows x (B*H). 8 warps, each warp m16 x n64.
// Q, K, V, P all single fp16. K via ldmatrix.x4 (j-pairs),
// V via ldmatrix.x4.trans (jd-pairs).
// 3-stage cp.async pipeline, one sync per tile, 2 CTAs/SM (74 KB smem).
// ---------------------------------------------------------------------------
#define KPITCH 144                       // bytes per 64-dim fp16 row (72 fp16)
#define QT (128 * KPITCH)                // 18432 B (Q tile, single)
#define CT (64 * KPITCH)                 // 9216 B per K or V tile
#define KVNST 3
#define ATT_SMEM (QT + KVNST * 2 * CT)   // 73728 B

static __device__ __forceinline__ void issue_kv(
    uint32_t dst, const __half* __restrict__ Kg, const __half* __restrict__ Vg,
    size_t gbase, int k0, int tid)
{
    const int r = tid >> 2;
    const int c = tid & 3;
    const size_t g = gbase + (size_t)(k0 + r) * HD;
#pragma unroll
    for (int cc = 0; cc < 2; cc++) {
        const int ch = c + cc * 4;
        const uint32_t so = (uint32_t)(r * KPITCH + ch * 16);
        cp_async16(dst + 0 * CT + so, Kg + g + ch * 8);
        cp_async16(dst + 1 * CT + so, Vg + g + ch * 8);
    }
}

__global__ __launch_bounds__(256, 2)
void attn_mma_kernel(
    const __half* __restrict__ Qg,
    const __half* __restrict__ Kg, const __half* __restrict__ Vg,
    __half* __restrict__ Og)
{
    extern __shared__ char smem[];
    const uint32_t sb = smem_u32(smem);
    const uint32_t sQ = sb;                  // Q tile (single)
    const uint32_t sKV = sb + QT;            // KVNST stages of 2*CT

    const int tid = threadIdx.x;
    const int lane = tid & 31;
    const int w = tid >> 5;
    const int qb = (int)gridDim.x - 1 - (int)blockIdx.x;   // long blocks first
    const int bh = blockIdx.y;
    const int q0 = qb * 128;
    const size_t base = (size_t)bh * S_LEN * HD;

    // load Q tile (group 0)
    {
        const int r = tid >> 1;
        const int c0 = (tid & 1) * 4;
#pragma unroll
        for (int c = c0; c < c0 + 4; c++) {
            const uint32_t so = (uint32_t)(r * KPITCH + c * 16);
            cp_async16(sQ + so, Qg + base + (size_t)(q0 + r) * HD + c * 8);
        }
    }
    CP_COMMIT();

    const int nt = 2 * qb + 2;
    issue_kv(sKV + 0 * 2 * CT, Kg, Vg, base, 0, tid);
    CP_COMMIT();
    if (nt > 1) {
        issue_kv(sKV + 1 * 2 * CT, Kg, Vg, base, 64, tid);
    }
    CP_COMMIT();

    CP_WAIT2();          // Q done (kv0, kv1 may be pending)
    __syncthreads();

    // resident Q fragments (single fp16)
    const int wm = w * 16;
    uint32_t qf[4][4];
    {
        const uint32_t ab = sQ + (uint32_t)((wm + (lane & 15)) * KPITCH + (lane >> 4) * 16);
#pragma unroll
        for (int kk = 0; kk < 4; kk++)
            ldmatrix_x4(qf[kk], ab + kk * 32);
    }

    float o[8][4];
#pragma unroll
    for (int j = 0; j < 8; j++)
#pragma unroll
        for (int c = 0; c < 4; c++) o[j][c] = 0.f;
    float m0 = -1e30f, m1 = -1e30f, l0 = 0.f, l1 = 0.f;

    const uint32_t kb4_off = ((uint32_t)((lane >> 4) * 8 + (lane & 7))) * KPITCH
                           + (uint32_t)((lane >> 3) & 1) * 16;
    const uint32_t vb4_off = (uint32_t)(lane & 15) * KPITCH + (uint32_t)(lane >> 4) * 16;

    int stage = 0, wstage = 2 % KVNST;
    for (int it = 0; it < nt; it++) {
        CP_WAIT1();          // kv(it) done (<=1 pending: kv(it+1))
        __syncthreads();     // visible; all warps finished stage (it-1)
        if (it + 2 < nt) {
            issue_kv(sKV + wstage * 2 * CT, Kg, Vg, base, (it + 2) * 64, tid);
            CP_COMMIT();
        } else {
            CP_COMMIT();     // keep group counts uniform
        }

        const int k0 = it * 64;
        const bool active = (k0 <= q0 + wm + 15);
        if (active) {
            const uint32_t st = sKV + stage * 2 * CT;

            // ---- S = Q K^T (single fp16), K via x4 j-pairs ----
            float s[8][4];
#pragma unroll
            for (int j = 0; j < 8; j++)
#pragma unroll
                for (int c = 0; c < 4; c++) s[j][c] = 0.f;

            const uint32_t kb_ = st + kb4_off;
#pragma unroll
            for (int kk = 0; kk < 4; kk++) {
#pragma unroll
                for (int jp = 0; jp < 4; jp++) {
                    uint32_t k4[4];
                    ldmatrix_x4(k4, kb_ + (uint32_t)(jp * 16 * KPITCH + kk * 32));
                    const int j0 = jp * 2, j1 = j0 + 1;
                    mma_f16(s[j0], qf[kk], &k4[0]);
                    mma_f16(s[j1], qf[kk], &k4[2]);
                }
            }

            // ---- causal mask (log2 domain; Q pre-scaled) ----
            if (k0 + 63 > q0 + wm) {
#pragma unroll
                for (int j = 0; j < 8; j++)
#pragma unroll
                    for (int c = 0; c < 4; c++) {
                        const int kc = k0 + j * 8 + 2 * (lane & 3) + (c & 1);
                        const int rq = q0 + wm + (lane >> 2) + (c >> 1) * 8;
                        if (kc > rq) s[j][c] = -1e30f;
                    }
            }

            // ---- online softmax (exp2 domain) ----
            float mx0 = -1e30f, mx1 = -1e30f;
#pragma unroll
            for (int j = 0; j < 8; j++) {
                mx0 = fmaxf(mx0, fmaxf(s[j][0], s[j][1]));
                mx1 = fmaxf(mx1, fmaxf(s[j][2], s[j][3]));
            }
            mx0 = fmaxf(mx0, __shfl_xor_sync(0xffffffffu, mx0, 1));
            mx0 = fmaxf(mx0, __shfl_xor_sync(0xffffffffu, mx0, 2));
            mx1 = fmaxf(mx1, __shfl_xor_sync(0xffffffffu, mx1, 1));
            mx1 = fmaxf(mx1, __shfl_xor_sync(0xffffffffu, mx1, 2));

            const float mn0 = fmaxf(m0, mx0);
            const float mn1 = fmaxf(m1, mx1);
            const float f0 = ex2f(m0 - mn0);
            const float f1 = ex2f(m1 - mn1);
            m0 = mn0; m1 = mn1;

            float sum0 = 0.f, sum1 = 0.f;
#pragma unroll
            for (int j = 0; j < 8; j++) {
                s[j][0] = ex2f(s[j][0] - mn0);
                s[j][1] = ex2f(s[j][1] - mn0);
                s[j][2] = ex2f(s[j][2] - mn1);
                s[j][3] = ex2f(s[j][3] - mn1);
                sum0 += s[j][0] + s[j][1];
                sum1 += s[j][2] + s[j][3];
            }
            sum0 += __shfl_xor_sync(0xffffffffu, sum0, 1);
            sum0 += __shfl_xor_sync(0xffffffffu, sum0, 2);
            sum1 += __shfl_xor_sync(0xffffffffu, sum1, 1);
            sum1 += __shfl_xor_sync(0xffffffffu, sum1, 2);
            l0 = l0 * f0 + sum0;
            l1 = l1 * f1 + sum1;

#pragma unroll
            for (int j = 0; j < 8; j++) {
                o[j][0] *= f0; o[j][1] *= f0;
                o[j][2] *= f1; o[j][3] *= f1;
            }

            // ---- O += P V (single fp16 P), V via x4.trans ----
            const uint32_t vb_ = st + CT + vb4_off;
#pragma unroll
            for (int t = 0; t < 4; t++) {
                uint32_t ph[4];
#pragma unroll
                for (int half = 0; half < 2; half++) {
                    const float* sp = s[2 * t + half];
                    __half2 h01 = __floats2half2_rn(sp[0], sp[1]);
                    __half2 h23 = __floats2half2_rn(sp[2], sp[3]);
                    ph[2 * half + 0] = *(uint32_t*)&h01;
                    ph[2 * half + 1] = *(uint32_t*)&h23;
                }
#pragma unroll
                for (int jq = 0; jq < 4; jq++) {
                    uint32_t v4[4];
                    ldmatrix_x4_trans(v4, vb_ + (uint32_t)(16 * t * KPITCH + jq * 32));
                    const int jd0 = jq * 2, jd1 = jd0 + 1;
                    mma_f16(o[jd0], ph, &v4[0]);
                    mma_f16(o[jd1], ph, &v4[2]);
                }
            }
        }

        if (++stage == KVNST) stage = 0;
        if (++wstage == KVNST) wstage = 0;
    }

    // ---- epilogue: normalize, write single fp16 [M,E] ----
    const int b = bh >> 4;
    const int h = bh & 15;
    const float inv0 = 1.0f / l0;
    const float inv1 = 1.0f / l1;
    const int r0 = b * S_LEN + q0 + wm + (lane >> 2);
    const int colb = h * HD + 2 * (lane & 3);
#pragma unroll
    for (int jd = 0; jd < 8; jd++) {
        const int col = colb + jd * 8;
#pragma unroll
        for (int h2 = 0; h2 < 2; h2++) {
            const float inv = h2 ? inv1 : inv0;
            const float vx = o[jd][h2 * 2 + 0] * inv;
            const float vy = o[jd][h2 * 2 + 1] * inv;
            const size_t off = (size_t)(r0 + h2 * 8) * EMB + col;
            *(__half2*)&Og[off] = __floats2half2_rn(vx, vy);
        }
    }
}

// ---------------------------------------------------------------------------
// Launch
// ---------------------------------------------------------------------------
extern "C" void kernel_launch(void* const* d_in, const int* in_sizes, int n_in,
                              void* d_out, int out_size)
{
    const float* x      = (const float*)d_in[0];
    const float* W_qkv  = (const float*)d_in[1];
    const float* b_qkv  = (const float*)d_in[2];
    const float* W_proj = (const float*)d_in[3];
    const float* b_proj = (const float*)d_in[4];
    float* out = (float*)d_out;

    __half *Ag, *WQ, *WP, *Qg, *Kg, *Vg;
    cudaGetSymbolAddress((void**)&Ag, g_A);
    cudaGetSymbolAddress((void**)&WQ, g_WQ);
    cudaGetSymbolAddress((void**)&WP, g_WP);
    cudaGetSymbolAddress((void**)&Qg, g_Q);
    cudaGetSymbolAddress((void**)&Kg, g_K);
    cudaGetSymbolAddress((void**)&Vg, g_V);

    cudaFuncSetAttribute(gemm_f16_kernel,
                         cudaFuncAttributeMaxDynamicSharedMemorySize, GEMM_SMEM);
    cudaFuncSetAttribute(attn_mma_kernel,
                         cudaFuncAttributeMaxDynamicSharedMemorySize, ATT_SMEM);

    // 0) pre-convert weights (transposed, fp16) and input activations (fp16)
    {
        dim3 blk(32, 8);
        conv_wT_kernel<<<dim3(3 * EMB / 32, EMB / 32), blk>>>(W_qkv, WQ, EMB, 3 * EMB);
        conv_wT_kernel<<<dim3(EMB / 32, EMB / 32), blk>>>(W_proj, WP, EMB, EMB);
        const int n4 = MTOT * EMB / 4;
        conv_act_kernel<<<n4 / 256, 256>>>((const float4*)x, (__half2*)Ag, n4);
    }

    // 1) QKV projection (single fp16, 256x128 tiles) -> Q (pre-scaled), K, V
    gemm_f16_kernel<<<dim3(3 * EMB / 128, MTOT / 256), 512, GEMM_SMEM>>>(
        Ag, WQ, b_qkv, nullptr, MTOT, 3 * EMB, EMB, 1, Kg, Qg, Vg);

    // 2) fused causal flash attention (single fp16) -> fp16 Ag
    attn_mma_kernel<<<dim3(S_LEN / 128, BATCH * NH), 256, ATT_SMEM>>>(
        Qg, Kg, Vg, Ag);

    // 3) output projection (single fp16, 256x128 tiles) -> fp32 out
    gemm_f16_kernel<<<dim3(EMB / 128, MTOT / 256), 512, GEMM_SMEM>>>(
        Ag, WP, b_proj, out, MTOT, EMB, EMB, 0, nullptr, nullptr, nullptr);
}

// round 16
// speedup vs baseline: 1.0037x; 1.0037x over previous
#include <cuda_runtime.h>
#include <cuda_bf16.h>
#include <cuda_fp16.h>
#include <cstdint>

#define BATCH 4
#define S_LEN 2048
#define EMB   1024
#define NH    16
#define HD    64
#define MTOT  (BATCH * S_LEN)   // 8192

// ---------------------------------------------------------------------------
// Device-global scratch (allocation-free requirement)
// ---------------------------------------------------------------------------
static __device__ __half g_A [MTOT * EMB];               // GEMM A (single fp16)
static __device__ __half g_WQ[3 * EMB * EMB];            // W_qkv^T fp16 [N=3072,K=1024]
static __device__ __half g_WP[EMB * EMB];                // W_proj^T fp16 [N=1024,K=1024]

static __device__ __half g_Q [BATCH * NH * S_LEN * HD];  // Q single fp16 (pre-scaled)
static __device__ __half g_K [BATCH * NH * S_LEN * HD];  // K single fp16
static __device__ __half g_V [BATCH * NH * S_LEN * HD];  // V single fp16

// ---------------------------------------------------------------------------
// Portable PTX helpers (compute_100-safe)
// ---------------------------------------------------------------------------
static __device__ __forceinline__ uint32_t smem_u32(const void* p) {
    uint32_t a;
    asm("{ .reg .u64 t; cvta.to.shared.u64 t, %1; cvt.u32.u64 %0, t; }" : "=r"(a) : "l"(p));
    return a;
}
static __device__ __forceinline__ void cp_async16(uint32_t dst, const void* src) {
    asm volatile("cp.async.cg.shared.global [%0], [%1], 16;" :: "r"(dst), "l"(src) : "memory");
}
#define CP_COMMIT() asm volatile("cp.async.commit_group;" ::: "memory")
#define CP_WAIT1()  asm volatile("cp.async.wait_group 1;" ::: "memory")
#define CP_WAIT2()  asm volatile("cp.async.wait_group 2;" ::: "memory")

static __device__ __forceinline__ void ldmatrix_x4(uint32_t* r, uint32_t addr) {
    asm volatile("ldmatrix.sync.aligned.m8n8.x4.shared.b16 {%0,%1,%2,%3}, [%4];"
                 : "=r"(r[0]), "=r"(r[1]), "=r"(r[2]), "=r"(r[3]) : "r"(addr));
}
static __device__ __forceinline__ void ldmatrix_x4_trans(uint32_t* r, uint32_t addr) {
    asm volatile("ldmatrix.sync.aligned.m8n8.x4.trans.shared.b16 {%0,%1,%2,%3}, [%4];"
                 : "=r"(r[0]), "=r"(r[1]), "=r"(r[2]), "=r"(r[3]) : "r"(addr));
}
static __device__ __forceinline__ void mma_f16(float* d, const uint32_t* a, const uint32_t* b) {
    asm volatile("mma.sync.aligned.m16n8k16.row.col.f32.f16.f16.f32 "
                 "{%0,%1,%2,%3}, {%4,%5,%6,%7}, {%8,%9}, {%0,%1,%2,%3};"
                 : "+f"(d[0]), "+f"(d[1]), "+f"(d[2]), "+f"(d[3])
                 : "r"(a[0]), "r"(a[1]), "r"(a[2]), "r"(a[3]), "r"(b[0]), "r"(b[1]));
}
static __device__ __forceinline__ float ex2f(float x) {
    float y;
    asm("ex2.approx.ftz.f32 %0, %1;" : "=f"(y) : "f"(x));
    return y;
}

// ---------------------------------------------------------------------------
// Pre-processing kernels
// ---------------------------------------------------------------------------
__global__ void conv_act_kernel(const float4* __restrict__ in,
                                __half2* __restrict__ o16, int n4)
{
    int i = blockIdx.x * 256 + threadIdx.x;
    if (i >= n4) return;
    float4 v = in[i];
    o16[i * 2 + 0] = __floats2half2_rn(v.x, v.y);
    o16[i * 2 + 1] = __floats2half2_rn(v.z, v.w);
}

// W [K,N] fp32 -> W^T [N,K] fp16 (tiled transpose)
__global__ void conv_wT_kernel(const float* __restrict__ W,
                               __half* __restrict__ Th, int Kd, int Nd)
{
    __shared__ float t[32][33];
    const int n0 = blockIdx.x * 32, k0 = blockIdx.y * 32;
    const int tx = threadIdx.x, ty = threadIdx.y;
#pragma unroll
    for (int j = 0; j < 32; j += 8)
        t[ty + j][tx] = W[(size_t)(k0 + ty + j) * Nd + n0 + tx];
    __syncthreads();
#pragma unroll
    for (int j = 0; j < 32; j += 8) {
        float v = t[tx][ty + j];
        Th[(size_t)(n0 + ty + j) * Kd + k0 + tx] = __float2half_rn(v);
    }
}

// ---------------------------------------------------------------------------
// Single-fp16 mma.sync GEMM — R13 (best measured): 128x128 CTA tile,
// 256 threads (8 warps = 4m x 2n, warp tile 32x64), BK=64, pitch-72 rows,
// 2-stage cp.async pipeline, 2 CTAs/SM.
// mode 0: fp32 C (+bias). mode 1: QKV epilogue -> Q (pre-scaled), K, V
// all single fp16 in [B,H,S,D].
// ---------------------------------------------------------------------------
#define BK      64
#define GP      144                      // bytes per 64-fp16 row (72 fp16)
#define TILE_B  (128 * GP)               // 18432 B
#define STAGE_B (2 * TILE_B)             // 36864 B (A, W)
#define GEMM_SMEM (2 * STAGE_B)          // 73728 B

#define QSCALE  0.1803368801111244f      // 0.125 * log2(e)

static __device__ __forceinline__ void issue_stage(
    uint32_t sstage, const __half* __restrict__ Ag, const __half* __restrict__ Bg,
    int bm0, int bn0, int K, int kof, int tid)
{
    const int r  = tid >> 1;              // 0..127
    const int c0 = (tid & 1) * 4;         // 4 chunks of 16B each
    const size_t ga = (size_t)(bm0 + r) * K + kof;
    const size_t gb = (size_t)(bn0 + r) * K + kof;
    const uint32_t so = (uint32_t)(r * GP);
#pragma unroll
    for (int cc = 0; cc < 4; cc++) {
        const int c = c0 + cc;
        cp_async16(sstage + 0 * TILE_B + so + c * 16, Ag + ga + c * 8);
        cp_async16(sstage + 1 * TILE_B + so + c * 16, Bg + gb + c * 8);
    }
}

__global__ __launch_bounds__(256, 2)
void gemm_f16_kernel(
    const __half* __restrict__ Ag, const __half* __restrict__ Bg,
    const float* __restrict__ bias, float* __restrict__ C,
    int M, int N, int K, int mode,
    __half* __restrict__ kg, __half* __restrict__ qg, __half* __restrict__ vg)
{
    extern __shared__ char smem[];
    const uint32_t sbase = smem_u32(smem);
    const int tid  = threadIdx.x;
    const int wid  = tid >> 5;
    const int lane = tid & 31;
    const int bm0 = blockIdx.y * 128;
    const int bn0 = blockIdx.x * 128;

    const int wm = (wid & 3) * 32;       // warp m offset (4 positions)
    const int wn = (wid >> 2) * 64;      // warp n offset (2 positions)

    float acc[2][8][4];
#pragma unroll
    for (int i = 0; i < 2; i++)
#pragma unroll
        for (int j = 0; j < 8; j++)
#pragma unroll
            for (int c = 0; c < 4; c++) acc[i][j][c] = 0.f;

    const int nk = K / BK;   // 16

    issue_stage(sbase + 0 * STAGE_B, Ag, Bg, bm0, bn0, K, 0, tid);
    CP_COMMIT();
    issue_stage(sbase + 1 * STAGE_B, Ag, Bg, bm0, bn0, K, BK, tid);
    CP_COMMIT();

    const uint32_t a_off = (uint32_t)(lane & 15) * GP + (uint32_t)(lane >> 4) * 16;
    const uint32_t b_off = ((uint32_t)((lane >> 4) * 8 + (lane & 7))) * GP
                         + (uint32_t)((lane >> 3) & 1) * 16;

    for (int it = 0; it < nk; it++) {
        CP_WAIT1();
        __syncthreads();
        const uint32_t st = sbase + (it & 1) * STAGE_B;
#pragma unroll
        for (int ks = 0; ks < 4; ks++) {
            uint32_t a4[2][4];
#pragma unroll
            for (int i = 0; i < 2; i++) {
                const uint32_t ro = st + (uint32_t)(wm + i * 16) * GP
                                  + (uint32_t)(ks * 32) + a_off;
                ldmatrix_x4(a4[i], ro);
            }
#pragma unroll
            for (int jp = 0; jp < 4; jp++) {
                uint32_t b4[4];
                const uint32_t ro = st + TILE_B + (uint32_t)(wn + jp * 16) * GP
                                  + (uint32_t)(ks * 32) + b_off;
                ldmatrix_x4(b4, ro);
                const int j0 = jp * 2, j1 = j0 + 1;
#pragma unroll
                for (int i = 0; i < 2; i++) {
                    mma_f16(acc[i][j0], a4[i], &b4[0]);
                    mma_f16(acc[i][j1], a4[i], &b4[2]);
                }
            }
        }
        __syncthreads();
        if (it + 2 < nk)
            issue_stage(st, Ag, Bg, bm0, bn0, K, (it + 2) * BK, tid);
        CP_COMMIT();
    }

    const int lr = lane >> 2;
    const int lc = (lane & 3) * 2;
#pragma unroll
    for (int i = 0; i < 2; i++) {
#pragma unroll
        for (int j = 0; j < 8; j++) {
            const int col = bn0 + wn + j * 8 + lc;
            const float bx = bias[col], by = bias[col + 1];
#pragma unroll
            for (int h2 = 0; h2 < 2; h2++) {
                const int row = bm0 + wm + i * 16 + lr + h2 * 8;
                float vx = acc[i][j][h2 * 2 + 0] + bx;
                float vy = acc[i][j][h2 * 2 + 1] + by;
                if (mode == 0) {
                    float2 v = make_float2(vx, vy);
                    *(float2*)&C[(size_t)row * N + col] = v;
                } else {
                    const int sec = col >> 10;
                    const int hh  = (col >> 6) & 15;
                    const int d   = col & 63;
                    const int b_  = row >> 11;
                    const int s   = row & 2047;
                    const size_t off = (((size_t)(b_ * NH + hh)) * S_LEN + s) * HD + d;
                    if (sec == 1) { vx *= QSCALE; vy *= QSCALE; }
                    __half* dst = (sec == 0) ? kg : ((sec == 1) ? qg : vg);
                    *(__half2*)&dst[off] = __floats2half2_rn(vx, vy);
                }
            }
        }
    }
}

// ---------------------------------------------------------------------------
// Flash attention (causal), single-fp16 operands (R13 per-warp code).
// NEW: 256 q-rows per block, 512 threads (16 warps, each m16 x n64) —
// halves KV global traffic and KV LDSM per unit work. 1 CTA/SM (92 KB),
// same 16 warps/SM as before.
// ---------------------------------------------------------------------------
#define KPITCH 144                       // bytes per 64-dim fp16 row (72 fp16)
#define QT2 (256 * KPITCH)               // 36864 B (Q tile, 256 rows)
#define CT (64 * KPITCH)                 // 9216 B per K or V tile
#define KVNST 3
#define ATT_SMEM (QT2 + KVNST * 2 * CT)  // 92160 B

static __device__ __forceinline__ void issue_kv(
    uint32_t dst, const __half* __restrict__ Kg, const __half* __restrict__ Vg,
    size_t gbase, int k0, int tid)
{
    // 64 rows x 8 chunks = 512 chunks; one K and one V chunk per thread
    const int r = tid >> 3;
    const int c = tid & 7;
    const size_t g = gbase + (size_t)(k0 + r) * HD + c * 8;
    const uint32_t so = (uint32_t)(r * KPITCH + c * 16);
    cp_async16(dst + 0 * CT + so, Kg + g);
    cp_async16(dst + 1 * CT + so, Vg + g);
}

__global__ __launch_bounds__(512, 1)
void attn_mma_kernel(
    const __half* __restrict__ Qg,
    const __half* __restrict__ Kg, const __half* __restrict__ Vg,
    __half* __restrict__ Og)
{
    extern __shared__ char smem[];
    const uint32_t sb = smem_u32(smem);
    const uint32_t sQ = sb;                  // Q tile (256 rows)
    const uint32_t sKV = sb + QT2;           // KVNST stages of 2*CT

    const int tid = threadIdx.x;
    const int lane = tid & 31;
    const int w = tid >> 5;                  // 0..15
    const int qb = (int)gridDim.x - 1 - (int)blockIdx.x;   // long blocks first
    const int bh = blockIdx.y;
    const int q0 = qb * 256;
    const size_t base = (size_t)bh * S_LEN * HD;

    // load Q tile: 256 rows x 8 chunks = 2048 chunks; 4 per thread
    {
        const int r = tid >> 1;              // 0..255
        const int c0 = (tid & 1) * 4;
#pragma unroll
        for (int c = c0; c < c0 + 4; c++) {
            const uint32_t so = (uint32_t)(r * KPITCH + c * 16);
            cp_async16(sQ + so, Qg + base + (size_t)(q0 + r) * HD + c * 8);
        }
    }
    CP_COMMIT();

    const int nt = 4 * qb + 4;
    issue_kv(sKV + 0 * 2 * CT, Kg, Vg, base, 0, tid);
    CP_COMMIT();
    issue_kv(sKV + 1 * 2 * CT, Kg, Vg, base, 64, tid);
    CP_COMMIT();

    CP_WAIT2();          // Q done (kv0, kv1 may be pending)
    __syncthreads();

    // resident Q fragments (single fp16), warp covers rows q0+wm..+15
    const int wm = w * 16;
    uint32_t qf[4][4];
    {
        const uint32_t ab = sQ + (uint32_t)((wm + (lane & 15)) * KPITCH + (lane >> 4) * 16);
#pragma unroll
        for (int kk = 0; kk < 4; kk++)
            ldmatrix_x4(qf[kk], ab + kk * 32);
    }

    float o[8][4];
#pragma unroll
    for (int j = 0; j < 8; j++)
#pragma unroll
        for (int c = 0; c < 4; c++) o[j][c] = 0.f;
    float m0 = -1e30f, m1 = -1e30f, l0 = 0.f, l1 = 0.f;

    const uint32_t kb4_off = ((uint32_t)((lane >> 4) * 8 + (lane & 7))) * KPITCH
                           + (uint32_t)((lane >> 3) & 1) * 16;
    const uint32_t vb4_off = (uint32_t)(lane & 15) * KPITCH + (uint32_t)(lane >> 4) * 16;

    int stage = 0, wstage = 2 % KVNST;
    for (int it = 0; it < nt; it++) {
        CP_WAIT1();          // kv(it) done (<=1 pending: kv(it+1))
        __syncthreads();     // visible; all warps finished stage (it-1)
        if (it + 2 < nt) {
            issue_kv(sKV + wstage * 2 * CT, Kg, Vg, base, (it + 2) * 64, tid);
            CP_COMMIT();
        } else {
            CP_COMMIT();     // keep group counts uniform
        }

        const int k0 = it * 64;
        const bool active = (k0 <= q0 + wm + 15);
        if (active) {
            const uint32_t st = sKV + stage * 2 * CT;

            // ---- S = Q K^T (single fp16), K via x4 j-pairs ----
            float s[8][4];
#pragma unroll
            for (int j = 0; j < 8; j++)
#pragma unroll
                for (int c = 0; c < 4; c++) s[j][c] = 0.f;

            const uint32_t kb_ = st + kb4_off;
#pragma unroll
            for (int kk = 0; kk < 4; kk++) {
#pragma unroll
                for (int jp = 0; jp < 4; jp++) {
                    uint32_t k4[4];
                    ldmatrix_x4(k4, kb_ + (uint32_t)(jp * 16 * KPITCH + kk * 32));
                    const int j0 = jp * 2, j1 = j0 + 1;
                    mma_f16(s[j0], qf[kk], &k4[0]);
                    mma_f16(s[j1], qf[kk], &k4[2]);
                }
            }

            // ---- causal mask (log2 domain; Q pre-scaled) ----
            if (k0 + 63 > q0 + wm) {
#pragma unroll
                for (int j = 0; j < 8; j++)
#pragma unroll
                    for (int c = 0; c < 4; c++) {
                        const int kc = k0 + j * 8 + 2 * (lane & 3) + (c & 1);
                        const int rq = q0 + wm + (lane >> 2) + (c >> 1) * 8;
                        if (kc > rq) s[j][c] = -1e30f;
                    }
            }

            // ---- online softmax (exp2 domain) ----
            float mx0 = -1e30f, mx1 = -1e30f;
#pragma unroll
            for (int j = 0; j < 8; j++) {
                mx0 = fmaxf(mx0, fmaxf(s[j][0], s[j][1]));
                mx1 = fmaxf(mx1, fmaxf(s[j][2], s[j][3]));
            }
            mx0 = fmaxf(mx0, __shfl_xor_sync(0xffffffffu, mx0, 1));
            mx0 = fmaxf(mx0, __shfl_xor_sync(0xffffffffu, mx0, 2));
            mx1 = fmaxf(mx1, __shfl_xor_sync(0xffffffffu, mx1, 1));
            mx1 = fmaxf(mx1, __shfl_xor_sync(0xffffffffu, mx1, 2));

            const float mn0 = fmaxf(m0, mx0);
            const float mn1 = fmaxf(m1, mx1);
            const float f0 = ex2f(m0 - mn0);
            const float f1 = ex2f(m1 - mn1);
            m0 = mn0; m1 = mn1;

            float sum0 = 0.f, sum1 = 0.f;
#pragma unroll
            for (int j = 0; j < 8; j++) {
                s[j][0] = ex2f(s[j][0] - mn0);
                s[j][1] = ex2f(s[j][1] - mn0);
                s[j][2] = ex2f(s[j][2] - mn1);
                s[j][3] = ex2f(s[j][3] - mn1);
                sum0 += s[j][0] + s[j][1];
                sum1 += s[j][2] + s[j][3];
            }
            sum0 += __shfl_xor_sync(0xffffffffu, sum0, 1);
            sum0 += __shfl_xor_sync(0xffffffffu, sum0, 2);
            sum1 += __shfl_xor_sync(0xffffffffu, sum1, 1);
            sum1 += __shfl_xor_sync(0xffffffffu, sum1, 2);
            l0 = l0 * f0 + sum0;
            l1 = l1 * f1 + sum1;

#pragma unroll
            for (int j = 0; j < 8; j++) {
                o[j][0] *= f0; o[j][1] *= f0;
                o[j][2] *= f1; o[j][3] *= f1;
            }

            // ---- O += P V (single fp16 P), V via x4.trans ----
            const uint32_t vb_ = st + CT + vb4_off;
#pragma unroll
            for (int t = 0; t < 4; t++) {
                uint32_t ph[4];
#pragma unroll
                for (int half = 0; half < 2; half++) {
                    const float* sp = s[2 * t + half];
                    __half2 h01 = __floats2half2_rn(sp[0], sp[1]);
                    __half2 h23 = __floats2half2_rn(sp[2], sp[3]);
                    ph[2 * half + 0] = *(uint32_t*)&h01;
                    ph[2 * half + 1] = *(uint32_t*)&h23;
                }
#pragma unroll
                for (int jq = 0; jq < 4; jq++) {
                    uint32_t v4[4];
                    ldmatrix_x4_trans(v4, vb_ + (uint32_t)(16 * t * KPITCH + jq * 32));
                    const int jd0 = jq * 2, jd1 = jd0 + 1;
                    mma_f16(o[jd0], ph, &v4[0]);
                    mma_f16(o[jd1], ph, &v4[2]);
                }
            }
        }

        if (++stage == KVNST) stage = 0;
        if (++wstage == KVNST) wstage = 0;
    }

    // ---- epilogue: normalize, write single fp16 [M,E] ----
    const int b = bh >> 4;
    const int h = bh & 15;
    const float inv0 = 1.0f / l0;
    const float inv1 = 1.0f / l1;
    const int r0 = b * S_LEN + q0 + wm + (lane >> 2);
    const int colb = h * HD + 2 * (lane & 3);
#pragma unroll
    for (int jd = 0; jd < 8; jd++) {
        const int col = colb + jd * 8;
#pragma unroll
        for (int h2 = 0; h2 < 2; h2++) {
            const float inv = h2 ? inv1 : inv0;
            const float vx = o[jd][h2 * 2 + 0] * inv;
            const float vy = o[jd][h2 * 2 + 1] * inv;
            const size_t off = (size_t)(r0 + h2 * 8) * EMB + col;
            *(__half2*)&Og[off] = __floats2half2_rn(vx, vy);
        }
    }
}

// ---------------------------------------------------------------------------
// Launch
// ---------------------------------------------------------------------------
extern "C" void kernel_launch(void* const* d_in, const int* in_sizes, int n_in,
                              void* d_out, int out_size)
{
    const float* x      = (const float*)d_in[0];
    const float* W_qkv  = (const float*)d_in[1];
    const float* b_qkv  = (const float*)d_in[2];
    const float* W_proj = (const float*)d_in[3];
    const float* b_proj = (const float*)d_in[4];
    float* out = (float*)d_out;

    __half *Ag, *WQ, *WP, *Qg, *Kg, *Vg;
    cudaGetSymbolAddress((void**)&Ag, g_A);
    cudaGetSymbolAddress((void**)&WQ, g_WQ);
    cudaGetSymbolAddress((void**)&WP, g_WP);
    cudaGetSymbolAddress((void**)&Qg, g_Q);
    cudaGetSymbolAddress((void**)&Kg, g_K);
    cudaGetSymbolAddress((void**)&Vg, g_V);

    cudaFuncSetAttribute(gemm_f16_kernel,
                         cudaFuncAttributeMaxDynamicSharedMemorySize, GEMM_SMEM);
    cudaFuncSetAttribute(attn_mma_kernel,
                         cudaFuncAttributeMaxDynamicSharedMemorySize, ATT_SMEM);

    // 0) pre-convert weights (transposed, fp16) and input activations (fp16)
    {
        dim3 blk(32, 8);
        conv_wT_kernel<<<dim3(3 * EMB / 32, EMB / 32), blk>>>(W_qkv, WQ, EMB, 3 * EMB);
        conv_wT_kernel<<<dim3(EMB / 32, EMB / 32), blk>>>(W_proj, WP, EMB, EMB);
        const int n4 = MTOT * EMB / 4;
        conv_act_kernel<<<n4 / 256, 256>>>((const float4*)x, (__half2*)Ag, n4);
    }

    // 1) QKV projection (single fp16, R13 128x128 tiles) -> Q (pre-scaled), K, V
    gemm_f16_kernel<<<dim3(3 * EMB / 128, MTOT / 128), 256, GEMM_SMEM>>>(
        Ag, WQ, b_qkv, nullptr, MTOT, 3 * EMB, EMB, 1, Kg, Qg, Vg);

    // 2) fused causal flash attention (single fp16, 256-row Q blocks) -> fp16 Ag
    attn_mma_kernel<<<dim3(S_LEN / 256, BATCH * NH), 512, ATT_SMEM>>>(
        Qg, Kg, Vg, Ag);

    // 3) output projection (single fp16, R13 tiles) -> fp32 out
    gemm_f16_kernel<<<dim3(EMB / 128, MTOT / 128), 256, GEMM_SMEM>>>(
        Ag, WP, b_proj, out, MTOT, EMB, EMB, 0, nullptr, nullptr, nullptr);
}

// round 17
// speedup vs baseline: 1.0246x; 1.0208x over previous
#include <cuda_runtime.h>
#include <cuda_bf16.h>
#include <cuda_fp16.h>
#include <cstdint>

#define BATCH 4
#define S_LEN 2048
#define EMB   1024
#define NH    16
#define HD    64
#define MTOT  (BATCH * S_LEN)   // 8192

// ---------------------------------------------------------------------------
// Device-global scratch (allocation-free requirement)
// ---------------------------------------------------------------------------
static __device__ __half g_A [MTOT * EMB];               // GEMM A (single fp16)
static __device__ __half g_WQ[3 * EMB * EMB];            // W_qkv^T fp16 [N=3072,K=1024]
static __device__ __half g_WP[EMB * EMB];                // W_proj^T fp16 [N=1024,K=1024]

static __device__ __half g_Q [BATCH * NH * S_LEN * HD];  // Q single fp16 (pre-scaled)
static __device__ __half g_K [BATCH * NH * S_LEN * HD];  // K single fp16
static __device__ __half g_V [BATCH * NH * S_LEN * HD];  // V single fp16

// ---------------------------------------------------------------------------
// Portable PTX helpers (compute_100-safe)
// ---------------------------------------------------------------------------
static __device__ __forceinline__ uint32_t smem_u32(const void* p) {
    uint32_t a;
    asm("{ .reg .u64 t; cvta.to.shared.u64 t, %1; cvt.u32.u64 %0, t; }" : "=r"(a) : "l"(p));
    return a;
}
static __device__ __forceinline__ void cp_async16(uint32_t dst, const void* src) {
    asm volatile("cp.async.cg.shared.global [%0], [%1], 16;" :: "r"(dst), "l"(src) : "memory");
}
#define CP_COMMIT() asm volatile("cp.async.commit_group;" ::: "memory")
#define CP_WAIT1()  asm volatile("cp.async.wait_group 1;" ::: "memory")
#define CP_WAIT2()  asm volatile("cp.async.wait_group 2;" ::: "memory")

static __device__ __forceinline__ void ldmatrix_x4(uint32_t* r, uint32_t addr) {
    asm volatile("ldmatrix.sync.aligned.m8n8.x4.shared.b16 {%0,%1,%2,%3}, [%4];"
                 : "=r"(r[0]), "=r"(r[1]), "=r"(r[2]), "=r"(r[3]) : "r"(addr));
}
static __device__ __forceinline__ void ldmatrix_x4_trans(uint32_t* r, uint32_t addr) {
    asm volatile("ldmatrix.sync.aligned.m8n8.x4.trans.shared.b16 {%0,%1,%2,%3}, [%4];"
                 : "=r"(r[0]), "=r"(r[1]), "=r"(r[2]), "=r"(r[3]) : "r"(addr));
}
static __device__ __forceinline__ void mma_f16(float* d, const uint32_t* a, const uint32_t* b) {
    asm volatile("mma.sync.aligned.m16n8k16.row.col.f32.f16.f16.f32 "
                 "{%0,%1,%2,%3}, {%4,%5,%6,%7}, {%8,%9}, {%0,%1,%2,%3};"
                 : "+f"(d[0]), "+f"(d[1]), "+f"(d[2]), "+f"(d[3])
                 : "r"(a[0]), "r"(a[1]), "r"(a[2]), "r"(a[3]), "r"(b[0]), "r"(b[1]));
}
static __device__ __forceinline__ float ex2f(float x) {
    float y;
    asm("ex2.approx.ftz.f32 %0, %1;" : "=f"(y) : "f"(x));
    return y;
}

// ---------------------------------------------------------------------------
// Fused pre-processing: one launch handles both weight transposes + x convert.
// 256-thread blocks; task decoded from blockIdx.x.
//   [0, 3072):    W_qkv^T  (grid 96 x 32 tiles)
//   [3072, 4096): W_proj^T (grid 32 x 32 tiles)
//   [4096, 12288): x fp32 -> fp16 (8192 blocks x 256 float4)
// ---------------------------------------------------------------------------
__global__ __launch_bounds__(256) void conv_fused_kernel(
    const float* __restrict__ W_qkv, const float* __restrict__ W_proj,
    const float4* __restrict__ x,
    __half* __restrict__ WQ, __half* __restrict__ WP, __half2* __restrict__ Ag)
{
    __shared__ float t[32][33];
    const int bid = blockIdx.x;
    const int tid = threadIdx.x;

    if (bid < 4096) {
        const float* W;
        __half* Th;
        int Nd, bx, by;
        if (bid < 3072) {
            W = W_qkv; Th = WQ; Nd = 3 * EMB;
            bx = bid % 96; by = bid / 96;
        } else {
            const int b = bid - 3072;
            W = W_proj; Th = WP; Nd = EMB;
            bx = b % 32; by = b / 32;
        }
        const int n0 = bx * 32, k0 = by * 32;
        const int tx = tid & 31, ty = tid >> 5;
#pragma unroll
        for (int j = 0; j < 32; j += 8)
            t[ty + j][tx] = W[(size_t)(k0 + ty + j) * Nd + n0 + tx];
        __syncthreads();
#pragma unroll
        for (int j = 0; j < 32; j += 8) {
            float v = t[tx][ty + j];
            Th[(size_t)(n0 + ty + j) * EMB + k0 + tx] = __float2half_rn(v);
        }
    } else {
        const int i = (bid - 4096) * 256 + tid;   // < 2,097,152
        float4 v = x[i];
        Ag[i * 2 + 0] = __floats2half2_rn(v.x, v.y);
        Ag[i * 2 + 1] = __floats2half2_rn(v.z, v.w);
    }
}

// ---------------------------------------------------------------------------
// Single-fp16 mma.sync GEMM — R13 skeleton: 128x128 CTA tile, 256 threads
// (8 warps = 4m x 2n, warp tile 32x64), BK=64, pitch-72 rows, 2-stage
// cp.async pipeline, 2 CTAs/SM.
// NEW: 2-buffer B-fragment rotation — LDSM(jp+1) issued before MMAs(jp),
// raising LDSM->use distance past the shared-memory latency.
// mode 0: fp32 C (+bias). mode 1: QKV epilogue -> Q (pre-scaled), K, V
// all single fp16 in [B,H,S,D].
// ---------------------------------------------------------------------------
#define BK      64
#define GP      144                      // bytes per 64-fp16 row (72 fp16)
#define TILE_B  (128 * GP)               // 18432 B
#define STAGE_B (2 * TILE_B)             // 36864 B (A, W)
#define GEMM_SMEM (2 * STAGE_B)          // 73728 B

#define QSCALE  0.1803368801111244f      // 0.125 * log2(e)

static __device__ __forceinline__ void issue_stage(
    uint32_t sstage, const __half* __restrict__ Ag, const __half* __restrict__ Bg,
    int bm0, int bn0, int K, int kof, int tid)
{
    const int r  = tid >> 1;              // 0..127
    const int c0 = (tid & 1) * 4;         // 4 chunks of 16B each
    const size_t ga = (size_t)(bm0 + r) * K + kof;
    const size_t gb = (size_t)(bn0 + r) * K + kof;
    const uint32_t so = (uint32_t)(r * GP);
#pragma unroll
    for (int cc = 0; cc < 4; cc++) {
        const int c = c0 + cc;
        cp_async16(sstage + 0 * TILE_B + so + c * 16, Ag + ga + c * 8);
        cp_async16(sstage + 1 * TILE_B + so + c * 16, Bg + gb + c * 8);
    }
}

__global__ __launch_bounds__(256, 2)
void gemm_f16_kernel(
    const __half* __restrict__ Ag, const __half* __restrict__ Bg,
    const float* __restrict__ bias, float* __restrict__ C,
    int M, int N, int K, int mode,
    __half* __restrict__ kg, __half* __restrict__ qg, __half* __restrict__ vg)
{
    extern __shared__ char smem[];
    const uint32_t sbase = smem_u32(smem);
    const int tid  = threadIdx.x;
    const int wid  = tid >> 5;
    const int lane = tid & 31;
    const int bm0 = blockIdx.y * 128;
    const int bn0 = blockIdx.x * 128;

    const int wm = (wid & 3) * 32;       // warp m offset (4 positions)
    const int wn = (wid >> 2) * 64;      // warp n offset (2 positions)

    float acc[2][8][4];
#pragma unroll
    for (int i = 0; i < 2; i++)
#pragma unroll
        for (int j = 0; j < 8; j++)
#pragma unroll
            for (int c = 0; c < 4; c++) acc[i][j][c] = 0.f;

    const int nk = K / BK;   // 16

    issue_stage(sbase + 0 * STAGE_B, Ag, Bg, bm0, bn0, K, 0, tid);
    CP_COMMIT();
    issue_stage(sbase + 1 * STAGE_B, Ag, Bg, bm0, bn0, K, BK, tid);
    CP_COMMIT();

    const uint32_t a_off = (uint32_t)(lane & 15) * GP + (uint32_t)(lane >> 4) * 16;
    const uint32_t b_off = ((uint32_t)((lane >> 4) * 8 + (lane & 7))) * GP
                         + (uint32_t)((lane >> 3) & 1) * 16;

    for (int it = 0; it < nk; it++) {
        CP_WAIT1();
        __syncthreads();
        const uint32_t st = sbase + (it & 1) * STAGE_B;
#pragma unroll
        for (int ks = 0; ks < 4; ks++) {
            uint32_t a4[2][4];
#pragma unroll
            for (int i = 0; i < 2; i++) {
                const uint32_t ro = st + (uint32_t)(wm + i * 16) * GP
                                  + (uint32_t)(ks * 32) + a_off;
                ldmatrix_x4(a4[i], ro);
            }
            const uint32_t bb = st + TILE_B + (uint32_t)(ks * 32) + b_off;
            uint32_t bf0[4], bf1[4];
            // 2-buffer rotation: load jp+1 before consuming jp
            ldmatrix_x4(bf0, bb + (uint32_t)(wn + 0) * GP);       // jp0
            ldmatrix_x4(bf1, bb + (uint32_t)(wn + 16) * GP);      // jp1
            mma_f16(acc[0][0], a4[0], &bf0[0]);
            mma_f16(acc[0][1], a4[0], &bf0[2]);
            mma_f16(acc[1][0], a4[1], &bf0[0]);
            mma_f16(acc[1][1], a4[1], &bf0[2]);
            ldmatrix_x4(bf0, bb + (uint32_t)(wn + 32) * GP);      // jp2
            mma_f16(acc[0][2], a4[0], &bf1[0]);
            mma_f16(acc[0][3], a4[0], &bf1[2]);
            mma_f16(acc[1][2], a4[1], &bf1[0]);
            mma_f16(acc[1][3], a4[1], &bf1[2]);
            ldmatrix_x4(bf1, bb + (uint32_t)(wn + 48) * GP);      // jp3
            mma_f16(acc[0][4], a4[0], &bf0[0]);
            mma_f16(acc[0][5], a4[0], &bf0[2]);
            mma_f16(acc[1][4], a4[1], &bf0[0]);
            mma_f16(acc[1][5], a4[1], &bf0[2]);
            mma_f16(acc[0][6], a4[0], &bf1[0]);
            mma_f16(acc[0][7], a4[0], &bf1[2]);
            mma_f16(acc[1][6], a4[1], &bf1[0]);
            mma_f16(acc[1][7], a4[1], &bf1[2]);
        }
        __syncthreads();
        if (it + 2 < nk)
            issue_stage(st, Ag, Bg, bm0, bn0, K, (it + 2) * BK, tid);
        CP_COMMIT();
    }

    const int lr = lane >> 2;
    const int lc = (lane & 3) * 2;
#pragma unroll
    for (int i = 0; i < 2; i++) {
#pragma unroll
        for (int j = 0; j < 8; j++) {
            const int col = bn0 + wn + j * 8 + lc;
            const float bx = bias[col], by = bias[col + 1];
#pragma unroll
            for (int h2 = 0; h2 < 2; h2++) {
                const int row = bm0 + wm + i * 16 + lr + h2 * 8;
                float vx = acc[i][j][h2 * 2 + 0] + bx;
                float vy = acc[i][j][h2 * 2 + 1] + by;
                if (mode == 0) {
                    float2 v = make_float2(vx, vy);
                    *(float2*)&C[(size_t)row * N + col] = v;
                } else {
                    const int sec = col >> 10;
                    const int hh  = (col >> 6) & 15;
                    const int d   = col & 63;
                    const int b_  = row >> 11;
                    const int s   = row & 2047;
                    const size_t off = (((size_t)(b_ * NH + hh)) * S_LEN + s) * HD + d;
                    if (sec == 1) { vx *= QSCALE; vy *= QSCALE; }
                    __half* dst = (sec == 0) ? kg : ((sec == 1) ? qg : vg);
                    *(__half2*)&dst[off] = __floats2half2_rn(vx, vy);
                }
            }
        }
    }
}

// ---------------------------------------------------------------------------
// Flash attention (causal), single-fp16 operands — R13 geometry (128 q-rows,
// 256 threads, 2 CTAs/SM, 3-stage KV pipeline) with 2-buffer K/V fragment
// rotation in the QK and PV loops.
// ---------------------------------------------------------------------------
#define KPITCH 144                       // bytes per 64-dim fp16 row (72 fp16)
#define QT (128 * KPITCH)                // 18432 B (Q tile, single)
#define CT (64 * KPITCH)                 // 9216 B per K or V tile
#define KVNST 3
#define ATT_SMEM (QT + KVNST * 2 * CT)   // 73728 B

static __device__ __forceinline__ void issue_kv(
    uint32_t dst, const __half* __restrict__ Kg, const __half* __restrict__ Vg,
    size_t gbase, int k0, int tid)
{
    const int r = tid >> 2;
    const int c = tid & 3;
    const size_t g = gbase + (size_t)(k0 + r) * HD;
#pragma unroll
    for (int cc = 0; cc < 2; cc++) {
        const int ch = c + cc * 4;
        const uint32_t so = (uint32_t)(r * KPITCH + ch * 16);
        cp_async16(dst + 0 * CT + so, Kg + g + ch * 8);
        cp_async16(dst + 1 * CT + so, Vg + g + ch * 8);
    }
}

__global__ __launch_bounds__(256, 2)
void attn_mma_kernel(
    const __half* __restrict__ Qg,
    const __half* __restrict__ Kg, const __half* __restrict__ Vg,
    __half* __restrict__ Og)
{
    extern __shared__ char smem[];
    const uint32_t sb = smem_u32(smem);
    const uint32_t sQ = sb;                  // Q tile (single)
    const uint32_t sKV = sb + QT;            // KVNST stages of 2*CT

    const int tid = threadIdx.x;
    const int lane = tid & 31;
    const int w = tid >> 5;
    const int qb = (int)gridDim.x - 1 - (int)blockIdx.x;   // long blocks first
    const int bh = blockIdx.y;
    const int q0 = qb * 128;
    const size_t base = (size_t)bh * S_LEN * HD;

    // load Q tile (group 0)
    {
        const int r = tid >> 1;
        const int c0 = (tid & 1) * 4;
#pragma unroll
        for (int c = c0; c < c0 + 4; c++) {
            const uint32_t so = (uint32_t)(r * KPITCH + c * 16);
            cp_async16(sQ + so, Qg + base + (size_t)(q0 + r) * HD + c * 8);
        }
    }
    CP_COMMIT();

    const int nt = 2 * qb + 2;
    issue_kv(sKV + 0 * 2 * CT, Kg, Vg, base, 0, tid);
    CP_COMMIT();
    if (nt > 1) {
        issue_kv(sKV + 1 * 2 * CT, Kg, Vg, base, 64, tid);
    }
    CP_COMMIT();

    CP_WAIT2();          // Q done (kv0, kv1 may be pending)
    __syncthreads();

    // resident Q fragments (single fp16)
    const int wm = w * 16;
    uint32_t qf[4][4];
    {
        const uint32_t ab = sQ + (uint32_t)((wm + (lane & 15)) * KPITCH + (lane >> 4) * 16);
#pragma unroll
        for (int kk = 0; kk < 4; kk++)
            ldmatrix_x4(qf[kk], ab + kk * 32);
    }

    float o[8][4];
#pragma unroll
    for (int j = 0; j < 8; j++)
#pragma unroll
        for (int c = 0; c < 4; c++) o[j][c] = 0.f;
    float m0 = -1e30f, m1 = -1e30f, l0 = 0.f, l1 = 0.f;

    const uint32_t kb4_off = ((uint32_t)((lane >> 4) * 8 + (lane & 7))) * KPITCH
                           + (uint32_t)((lane >> 3) & 1) * 16;
    const uint32_t vb4_off = (uint32_t)(lane & 15) * KPITCH + (uint32_t)(lane >> 4) * 16;

    int stage = 0, wstage = 2 % KVNST;
    for (int it = 0; it < nt; it++) {
        CP_WAIT1();          // kv(it) done (<=1 pending: kv(it+1))
        __syncthreads();     // visible; all warps finished stage (it-1)
        if (it + 2 < nt) {
            issue_kv(sKV + wstage * 2 * CT, Kg, Vg, base, (it + 2) * 64, tid);
            CP_COMMIT();
        } else {
            CP_COMMIT();     // keep group counts uniform
        }

        const int k0 = it * 64;
        const bool active = (k0 <= q0 + wm + 15);
        if (active) {
            const uint32_t st = sKV + stage * 2 * CT;

            // ---- S = Q K^T (single fp16), 2-buffer K rotation ----
            float s[8][4];
#pragma unroll
            for (int j = 0; j < 8; j++)
#pragma unroll
                for (int c = 0; c < 4; c++) s[j][c] = 0.f;

            const uint32_t kb_ = st + kb4_off;
#pragma unroll
            for (int kk = 0; kk < 4; kk++) {
                const uint32_t kbk = kb_ + (uint32_t)(kk * 32);
                uint32_t kf0[4], kf1[4];
                ldmatrix_x4(kf0, kbk + 0 * 16 * KPITCH);   // jp0
                ldmatrix_x4(kf1, kbk + 1 * 16 * KPITCH);   // jp1
                mma_f16(s[0], qf[kk], &kf0[0]);
                mma_f16(s[1], qf[kk], &kf0[2]);
                ldmatrix_x4(kf0, kbk + 2 * 16 * KPITCH);   // jp2
                mma_f16(s[2], qf[kk], &kf1[0]);
                mma_f16(s[3], qf[kk], &kf1[2]);
                ldmatrix_x4(kf1, kbk + 3 * 16 * KPITCH);   // jp3
                mma_f16(s[4], qf[kk], &kf0[0]);
                mma_f16(s[5], qf[kk], &kf0[2]);
                mma_f16(s[6], qf[kk], &kf1[0]);
                mma_f16(s[7], qf[kk], &kf1[2]);
            }

            // ---- causal mask (log2 domain; Q pre-scaled) ----
            if (k0 + 63 > q0 + wm) {
#pragma unroll
                for (int j = 0; j < 8; j++)
#pragma unroll
                    for (int c = 0; c < 4; c++) {
                        const int kc = k0 + j * 8 + 2 * (lane & 3) + (c & 1);
                        const int rq = q0 + wm + (lane >> 2) + (c >> 1) * 8;
                        if (kc > rq) s[j][c] = -1e30f;
                    }
            }

            // ---- online softmax (exp2 domain) ----
            float mx0 = -1e30f, mx1 = -1e30f;
#pragma unroll
            for (int j = 0; j < 8; j++) {
                mx0 = fmaxf(mx0, fmaxf(s[j][0], s[j][1]));
                mx1 = fmaxf(mx1, fmaxf(s[j][2], s[j][3]));
            }
            mx0 = fmaxf(mx0, __shfl_xor_sync(0xffffffffu, mx0, 1));
            mx0 = fmaxf(mx0, __shfl_xor_sync(0xffffffffu, mx0, 2));
            mx1 = fmaxf(mx1, __shfl_xor_sync(0xffffffffu, mx1, 1));
            mx1 = fmaxf(mx1, __shfl_xor_sync(0xffffffffu, mx1, 2));

            const float mn0 = fmaxf(m0, mx0);
            const float mn1 = fmaxf(m1, mx1);
            const float f0 = ex2f(m0 - mn0);
            const float f1 = ex2f(m1 - mn1);
            m0 = mn0; m1 = mn1;

            float sum0 = 0.f, sum1 = 0.f;
#pragma unroll
            for (int j = 0; j < 8; j++) {
                s[j][0] = ex2f(s[j][0] - mn0);
                s[j][1] = ex2f(s[j][1] - mn0);
                s[j][2] = ex2f(s[j][2] - mn1);
                s[j][3] = ex2f(s[j][3] - mn1);
                sum0 += s[j][0] + s[j][1];
                sum1 += s[j][2] + s[j][3];
            }
            sum0 += __shfl_xor_sync(0xffffffffu, sum0, 1);
            sum0 += __shfl_xor_sync(0xffffffffu, sum0, 2);
            sum1 += __shfl_xor_sync(0xffffffffu, sum1, 1);
            sum1 += __shfl_xor_sync(0xffffffffu, sum1, 2);
            l0 = l0 * f0 + sum0;
            l1 = l1 * f1 + sum1;

#pragma unroll
            for (int j = 0; j < 8; j++) {
                o[j][0] *= f0; o[j][1] *= f0;
                o[j][2] *= f1; o[j][3] *= f1;
            }

            // ---- O += P V (single fp16 P), 2-buffer V rotation ----
            const uint32_t vb_ = st + CT + vb4_off;
#pragma unroll
            for (int t = 0; t < 4; t++) {
                uint32_t ph[4];
#pragma unroll
                for (int half = 0; half < 2; half++) {
                    const float* sp = s[2 * t + half];
                    __half2 h01 = __floats2half2_rn(sp[0], sp[1]);
                    __half2 h23 = __floats2half2_rn(sp[2], sp[3]);
                    ph[2 * half + 0] = *(uint32_t*)&h01;
                    ph[2 * half + 1] = *(uint32_t*)&h23;
                }
                const uint32_t vbt = vb_ + (uint32_t)(16 * t * KPITCH);
                uint32_t vf0[4], vf1[4];
                ldmatrix_x4_trans(vf0, vbt + 0 * 32);      // jq0
                ldmatrix_x4_trans(vf1, vbt + 1 * 32);      // jq1
                mma_f16(o[0], ph, &vf0[0]);
                mma_f16(o[1], ph, &vf0[2]);
                ldmatrix_x4_trans(vf0, vbt + 2 * 32);      // jq2
                mma_f16(o[2], ph, &vf1[0]);
                mma_f16(o[3], ph, &vf1[2]);
                ldmatrix_x4_trans(vf1, vbt + 3 * 32);      // jq3
                mma_f16(o[4], ph, &vf0[0]);
                mma_f16(o[5], ph, &vf0[2]);
                mma_f16(o[6], ph, &vf1[0]);
                mma_f16(o[7], ph, &vf1[2]);
            }
        }

        if (++stage == KVNST) stage = 0;
        if (++wstage == KVNST) wstage = 0;
    }

    // ---- epilogue: normalize, write single fp16 [M,E] ----
    const int b = bh >> 4;
    const int h = bh & 15;
    const float inv0 = 1.0f / l0;
    const float inv1 = 1.0f / l1;
    const int r0 = b * S_LEN + q0 + wm + (lane >> 2);
    const int colb = h * HD + 2 * (lane & 3);
#pragma unroll
    for (int jd = 0; jd < 8; jd++) {
        const int col = colb + jd * 8;
#pragma unroll
        for (int h2 = 0; h2 < 2; h2++) {
            const float inv = h2 ? inv1 : inv0;
            const float vx = o[jd][h2 * 2 + 0] * inv;
            const float vy = o[jd][h2 * 2 + 1] * inv;
            const size_t off = (size_t)(r0 + h2 * 8) * EMB + col;
            *(__half2*)&Og[off] = __floats2half2_rn(vx, vy);
        }
    }
}

// ---------------------------------------------------------------------------
// Launch
// ---------------------------------------------------------------------------
extern "C" void kernel_launch(void* const* d_in, const int* in_sizes, int n_in,
                              void* d_out, int out_size)
{
    const float* x      = (const float*)d_in[0];
    const float* W_qkv  = (const float*)d_in[1];
    const float* b_qkv  = (const float*)d_in[2];
    const float* W_proj = (const float*)d_in[3];
    const float* b_proj = (const float*)d_in[4];
    float* out = (float*)d_out;

    __half *Ag, *WQ, *WP, *Qg, *Kg, *Vg;
    cudaGetSymbolAddress((void**)&Ag, g_A);
    cudaGetSymbolAddress((void**)&WQ, g_WQ);
    cudaGetSymbolAddress((void**)&WP, g_WP);
    cudaGetSymbolAddress((void**)&Qg, g_Q);
    cudaGetSymbolAddress((void**)&Kg, g_K);
    cudaGetSymbolAddress((void**)&Vg, g_V);

    cudaFuncSetAttribute(gemm_f16_kernel,
                         cudaFuncAttributeMaxDynamicSharedMemorySize, GEMM_SMEM);
    cudaFuncSetAttribute(attn_mma_kernel,
                         cudaFuncAttributeMaxDynamicSharedMemorySize, ATT_SMEM);

    // 0) fused pre-conversion (weights transposed fp16 + x fp16), one launch
    conv_fused_kernel<<<12288, 256>>>(W_qkv, W_proj, (const float4*)x,
                                      WQ, WP, (__half2*)Ag);

    // 1) QKV projection (single fp16) -> Q (pre-scaled), K, V single fp16
    gemm_f16_kernel<<<dim3(3 * EMB / 128, MTOT / 128), 256, GEMM_SMEM>>>(
        Ag, WQ, b_qkv, nullptr, MTOT, 3 * EMB, EMB, 1, Kg, Qg, Vg);

    // 2) fused causal flash attention (single fp16) -> fp16 Ag
    attn_mma_kernel<<<dim3(S_LEN / 128, BATCH * NH), 256, ATT_SMEM>>>(
        Qg, Kg, Vg, Ag);

    // 3) output projection (single fp16) -> fp32 out
    gemm_f16_kernel<<<dim3(EMB / 128, MTOT / 128), 256, GEMM_SMEM>>>(
        Ag, WP, b_proj, out, MTOT, EMB, EMB, 0, nullptr, nullptr, nullptr);
}